// round 8
// baseline (speedup 1.0000x reference)
#include <cuda_runtime.h>
#include <math.h>
#include <stdint.h>

// Problem constants
#define BB 2
#define TT 2048
#define HH 16
#define DD 64
#define CC 1024

// Scratch (device globals: allocation-free per harness rules)
__device__ float g_qkv[BB * TT * 3 * CC];
__device__ float g_q[BB * HH * TT * DD];
__device__ float g_k[BB * HH * TT * DD];
__device__ float g_v[BB * HH * TT * DD];
__device__ float g_y[BB * TT * CC];

// ---------------------------------------------------------------------------
// tf32 / async helpers
// ---------------------------------------------------------------------------
__device__ __forceinline__ unsigned tf32u(float x) {
    unsigned u;
    asm("cvt.rna.tf32.f32 %0, %1;" : "=r"(u) : "f"(x));
    return u;
}
__device__ __forceinline__ float tf32f(float x) {
    return __uint_as_float(tf32u(x));
}

__device__ __forceinline__ void mma_tf32(float* d,
    unsigned a0, unsigned a1, unsigned a2, unsigned a3,
    unsigned b0, unsigned b1)
{
    asm volatile(
        "mma.sync.aligned.m16n8k8.row.col.f32.tf32.tf32.f32 "
        "{%0,%1,%2,%3}, {%4,%5,%6,%7}, {%8,%9}, {%0,%1,%2,%3};\n"
        : "+f"(d[0]), "+f"(d[1]), "+f"(d[2]), "+f"(d[3])
        : "r"(a0), "r"(a1), "r"(a2), "r"(a3), "r"(b0), "r"(b1));
}

__device__ __forceinline__ void cp16(uint32_t s, const void* g) {
    asm volatile("cp.async.cg.shared.global [%0], [%1], 16;\n" :: "r"(s), "l"(g));
}
__device__ __forceinline__ void cp_commit() {
    asm volatile("cp.async.commit_group;\n");
}
__device__ __forceinline__ void cp_wait0() {
    asm volatile("cp.async.wait_group 0;\n" ::: "memory");
}

// ---------------------------------------------------------------------------
// tf32 tensor-core GEMM v3: C[m][n] = sum_k A[m][k]*B[n][k]   (C = A*B^T)
// 256x128 block tile, BK=16, 512 threads (16 warps), warp tile 64x32.
// LDG->reg->cvt->STS double-buffered pipeline: tf32 stored in smem, so the
// hot fragment path is pure LDS + HMMA (no per-fragment cvt).
// ---------------------------------------------------------------------------
#define GP3 20   // smem row pitch: 20 -> conflict-free fragment LDS

__global__ __launch_bounds__(512) void mma_gemm_v3(
    const float* __restrict__ A, const float* __restrict__ Bm,
    float* __restrict__ Cm, int M, int N, int K)
{
    __shared__ __align__(16) unsigned As[2][256 * GP3];
    __shared__ __align__(16) unsigned Bs[2][128 * GP3];

    const int tid  = threadIdx.x;
    const int warp = tid >> 5;
    const int lane = tid & 31;
    const int g = lane >> 2;
    const int c = lane & 3;

    const int wm = (warp & 3) * 64;    // 4 warps along M
    const int wn = (warp >> 2) * 32;   // 4 warps along N

    const int bm = blockIdx.y * 256;
    const int bn = blockIdx.x * 128;

    // Load mapping: A tile 256x16 = 1024 float4 (2/thread); B 128x16 = 512 (1/thread)
    const int arow0 = tid >> 2;              // 0..127  (i=0), +128 for i=1
    const int acol  = (tid & 3) * 4;         // 0,4,8,12
    const int brow  = tid >> 2;              // 0..127
    const int bcol  = (tid & 3) * 4;

    const float* Ap0 = A + (size_t)(bm + arow0) * K + acol;
    const float* Ap1 = A + (size_t)(bm + arow0 + 128) * K + acol;
    const float* Bp  = Bm + (size_t)(bn + brow) * K + bcol;

    // Prologue: load k-tile 0, cvt, store to buf 0
    float4 a0 = *(const float4*)(Ap0);
    float4 a1 = *(const float4*)(Ap1);
    float4 b0 = *(const float4*)(Bp);
    {
        unsigned* ap = &As[0][arow0 * GP3 + acol];
        ap[0] = tf32u(a0.x); ap[1] = tf32u(a0.y); ap[2] = tf32u(a0.z); ap[3] = tf32u(a0.w);
        unsigned* ap2 = &As[0][(arow0 + 128) * GP3 + acol];
        ap2[0] = tf32u(a1.x); ap2[1] = tf32u(a1.y); ap2[2] = tf32u(a1.z); ap2[3] = tf32u(a1.w);
        unsigned* bp = &Bs[0][brow * GP3 + bcol];
        bp[0] = tf32u(b0.x); bp[1] = tf32u(b0.y); bp[2] = tf32u(b0.z); bp[3] = tf32u(b0.w);
    }
    __syncthreads();

    float acc[4][4][4];
#pragma unroll
    for (int i = 0; i < 4; i++)
#pragma unroll
        for (int j = 0; j < 4; j++)
#pragma unroll
            for (int r = 0; r < 4; r++) acc[i][j][r] = 0.0f;

    int buf = 0;
    for (int k0 = 0; k0 < K; k0 += 16) {
        const bool more = (k0 + 16 < K);
        if (more) {   // issue next tile's gmem loads early
            a0 = *(const float4*)(Ap0 + k0 + 16);
            a1 = *(const float4*)(Ap1 + k0 + 16);
            b0 = *(const float4*)(Bp + k0 + 16);
        }

        const unsigned* Ac = As[buf];
        const unsigned* Bc = Bs[buf];
#pragma unroll
        for (int ks = 0; ks < 2; ks++) {
            const int kk = ks * 8;
            unsigned af[4][4];
#pragma unroll
            for (int mt = 0; mt < 4; mt++) {
                const int r0 = wm + mt * 16 + g;
                af[mt][0] = Ac[r0 * GP3 + kk + c];
                af[mt][1] = Ac[(r0 + 8) * GP3 + kk + c];
                af[mt][2] = Ac[r0 * GP3 + kk + c + 4];
                af[mt][3] = Ac[(r0 + 8) * GP3 + kk + c + 4];
            }
            unsigned bf[4][2];
#pragma unroll
            for (int nt = 0; nt < 4; nt++) {
                const int n0 = wn + nt * 8 + g;
                bf[nt][0] = Bc[n0 * GP3 + kk + c];
                bf[nt][1] = Bc[n0 * GP3 + kk + c + 4];
            }
#pragma unroll
            for (int mt = 0; mt < 4; mt++)
#pragma unroll
                for (int nt = 0; nt < 4; nt++)
                    mma_tf32(acc[mt][nt], af[mt][0], af[mt][1], af[mt][2], af[mt][3],
                             bf[nt][0], bf[nt][1]);
        }

        if (more) {   // cvt + store next tile into the other buffer
            unsigned* ap = &As[buf ^ 1][arow0 * GP3 + acol];
            ap[0] = tf32u(a0.x); ap[1] = tf32u(a0.y); ap[2] = tf32u(a0.z); ap[3] = tf32u(a0.w);
            unsigned* ap2 = &As[buf ^ 1][(arow0 + 128) * GP3 + acol];
            ap2[0] = tf32u(a1.x); ap2[1] = tf32u(a1.y); ap2[2] = tf32u(a1.z); ap2[3] = tf32u(a1.w);
            unsigned* bp = &Bs[buf ^ 1][brow * GP3 + bcol];
            bp[0] = tf32u(b0.x); bp[1] = tf32u(b0.y); bp[2] = tf32u(b0.z); bp[3] = tf32u(b0.w);
            __syncthreads();
            buf ^= 1;
        }
    }

#pragma unroll
    for (int mt = 0; mt < 4; mt++) {
        const int r0 = bm + wm + mt * 16 + g;
#pragma unroll
        for (int nt = 0; nt < 4; nt++) {
            const int c0 = bn + wn + nt * 8 + 2 * c;
            *(float2*)(Cm + (size_t)r0 * N + c0) = make_float2(acc[mt][nt][0], acc[mt][nt][1]);
            *(float2*)(Cm + (size_t)(r0 + 8) * N + c0) = make_float2(acc[mt][nt][2], acc[mt][nt][3]);
        }
    }
}

// ---------------------------------------------------------------------------
// RMSNorm(q,k) + RoPE + head-split into [B,H,T,D]; outputs tf32-rounded.
// ---------------------------------------------------------------------------
__global__ void norm_rope_kernel(const float* __restrict__ qkv)
{
    const int lane = threadIdx.x;
    const int h = blockIdx.y * 4 + threadIdx.y;
    const int bt = blockIdx.x;
    const int b = bt / TT;
    const int t = bt % TT;

    const float* row = qkv + (size_t)bt * 3 * CC;
    float q0 = row[h * 64 + lane],           q1 = row[h * 64 + lane + 32];
    float k0 = row[CC + h * 64 + lane],      k1 = row[CC + h * 64 + lane + 32];
    float v0 = row[2 * CC + h * 64 + lane],  v1 = row[2 * CC + h * 64 + lane + 32];

    float qs = q0 * q0 + q1 * q1;
    float ks = k0 * k0 + k1 * k1;
#pragma unroll
    for (int w = 16; w >= 1; w >>= 1) {
        qs += __shfl_xor_sync(0xffffffffu, qs, w);
        ks += __shfl_xor_sync(0xffffffffu, ks, w);
    }
    const float eps = 1.1920929e-7f;
    float qr = rsqrtf(qs * (1.0f / 64.0f) + eps);
    float kr = rsqrtf(ks * (1.0f / 64.0f) + eps);
    q0 *= qr; q1 *= qr; k0 *= kr; k1 *= kr;

    float inv = powf(10000.0f, -(float)lane * (1.0f / 32.0f));
    float ang = (float)t * inv;
    float sn, cs;
    sincosf(ang, &sn, &cs);

    float qo0 = q0 * cs - q1 * sn;
    float qo1 = q1 * cs + q0 * sn;
    float ko0 = k0 * cs - k1 * sn;
    float ko1 = k1 * cs + k0 * sn;

    size_t o = (((size_t)b * HH + h) * TT + t) * DD;
    g_q[o + lane] = tf32f(qo0); g_q[o + lane + 32] = tf32f(qo1);
    g_k[o + lane] = tf32f(ko0); g_k[o + lane + 32] = tf32f(ko1);
    g_v[o + lane] = tf32f(v0);  g_v[o + lane + 32] = tf32f(v1);
}

// ---------------------------------------------------------------------------
// Causal flash attention, tf32 mma (unchanged from R5: 501us config).
// 256 threads (8 warps), 128 q-rows/block, 64-key tiles, cp.async double-buffer.
// ---------------------------------------------------------------------------
#define FKP 68
#define FVP 72
#define FLASH2_SMEM_BYTES ((128 * FKP + 2 * 64 * FKP + 2 * 64 * FVP) * 4)

__global__ __launch_bounds__(256) void flash_mma2()
{
    extern __shared__ __align__(16) float smem[];
    float* Ps  = smem;                       // [128][FKP]
    float* KsB = smem + 128 * FKP;           // [2][64][FKP]
    float* VsB = KsB + 2 * 64 * FKP;         // [2][64][FVP]

    const int tid  = threadIdx.x;
    const int warp = tid >> 5;
    const int lane = tid & 31;
    const int g = lane >> 2;
    const int c = lane & 3;
    const int qr = warp * 16;

    const int qt = gridDim.x - 1 - blockIdx.x;   // heavy tiles first
    const int bh = blockIdx.y;
    const int qbase = qt * 128;

    const float* Q = g_q + (size_t)bh * TT * DD;
    const float* K = g_k + (size_t)bh * TT * DD;
    const float* V = g_v + (size_t)bh * TT * DD;

    // Stage Q tile [128][64] into Ps
#pragma unroll
    for (int i = 0; i < 8; i++) {
        int idx = tid + i * 256;
        int r = idx >> 4, dv = (idx & 15) * 4;
        *(float4*)&Ps[r * FKP + dv] = *(const float4*)(Q + (size_t)(qbase + r) * 64 + dv);
    }

    const uint32_t ks_s = (uint32_t)__cvta_generic_to_shared(KsB);
    const uint32_t vs_s = (uint32_t)__cvta_generic_to_shared(VsB);

    // Prefetch K/V tile 0 into buffer 0
#pragma unroll
    for (int i = 0; i < 4; i++) {
        int idx = tid + i * 256;
        int r = idx >> 4, c4 = (idx & 15) * 4;
        cp16(ks_s + (uint32_t)(r * FKP + c4) * 4, K + (size_t)r * 64 + c4);
        cp16(vs_s + (uint32_t)(r * FVP + c4) * 4, V + (size_t)r * 64 + c4);
    }
    cp_commit();
    __syncthreads();

    // Extract Q A-fragments (per-warp rows)
    unsigned qf[8][4];
#pragma unroll
    for (int ks = 0; ks < 8; ks++) {
        const int kk = ks * 8;
        qf[ks][0] = __float_as_uint(Ps[(qr + g) * FKP + kk + c]);
        qf[ks][1] = __float_as_uint(Ps[(qr + g + 8) * FKP + kk + c]);
        qf[ks][2] = __float_as_uint(Ps[(qr + g) * FKP + kk + c + 4]);
        qf[ks][3] = __float_as_uint(Ps[(qr + g + 8) * FKP + kk + c + 4]);
    }

    float oacc[8][4];
#pragma unroll
    for (int nt = 0; nt < 8; nt++)
#pragma unroll
        for (int r = 0; r < 4; r++) oacc[nt][r] = 0.0f;
    float m0 = -1e30f, m1 = -1e30f, l0 = 0.0f, l1 = 0.0f;

    const int nkt = 2 * qt + 2;
    const int ktmax_w = 2 * qt + (warp >= 4 ? 1 : 0);
    const int q0i = qbase + qr + g;
    const int q1i = q0i + 8;

    for (int kt = 0; kt < nkt; kt++) {
        cp_wait0();
        __syncthreads();

        if (kt + 1 < nkt) {
            const int kb = (kt + 1) * 64;
            const uint32_t bo = (uint32_t)(((kt + 1) & 1) * 64);
#pragma unroll
            for (int i = 0; i < 4; i++) {
                int idx = tid + i * 256;
                int r = idx >> 4, c4 = (idx & 15) * 4;
                cp16(ks_s + ((bo + r) * FKP + c4) * 4, K + (size_t)(kb + r) * 64 + c4);
                cp16(vs_s + ((bo + r) * FVP + c4) * 4, V + (size_t)(kb + r) * 64 + c4);
            }
            cp_commit();
        }

        if (kt > ktmax_w) continue;

        const float* Ks = KsB + (kt & 1) * 64 * FKP;
        const float* Vs = VsB + (kt & 1) * 64 * FVP;

        // S = Q K^T
        float sacc[8][4];
#pragma unroll
        for (int nt = 0; nt < 8; nt++)
#pragma unroll
            for (int r = 0; r < 4; r++) sacc[nt][r] = 0.0f;

#pragma unroll
        for (int ks = 0; ks < 8; ks++) {
            const int kk = ks * 8;
#pragma unroll
            for (int nt = 0; nt < 8; nt++) {
                unsigned b0 = __float_as_uint(Ks[(nt * 8 + g) * FKP + kk + c]);
                unsigned b1 = __float_as_uint(Ks[(nt * 8 + g) * FKP + kk + c + 4]);
                mma_tf32(sacc[nt], qf[ks][0], qf[ks][1], qf[ks][2], qf[ks][3], b0, b1);
            }
        }

        // scale + causal mask
        const bool diag = (kt >= 2 * qt);
#pragma unroll
        for (int nt = 0; nt < 8; nt++) {
#pragma unroll
            for (int r = 0; r < 4; r++) sacc[nt][r] *= 0.125f;
            if (diag) {
                const int key0 = kt * 64 + nt * 8 + 2 * c;
                if (key0 > q0i)     sacc[nt][0] = -1e30f;
                if (key0 + 1 > q0i) sacc[nt][1] = -1e30f;
                if (key0 > q1i)     sacc[nt][2] = -1e30f;
                if (key0 + 1 > q1i) sacc[nt][3] = -1e30f;
            }
        }

        // online softmax
        float t0 = -1e30f, t1 = -1e30f;
#pragma unroll
        for (int nt = 0; nt < 8; nt++) {
            t0 = fmaxf(t0, fmaxf(sacc[nt][0], sacc[nt][1]));
            t1 = fmaxf(t1, fmaxf(sacc[nt][2], sacc[nt][3]));
        }
#pragma unroll
        for (int w = 1; w <= 2; w <<= 1) {
            t0 = fmaxf(t0, __shfl_xor_sync(0xffffffffu, t0, w));
            t1 = fmaxf(t1, __shfl_xor_sync(0xffffffffu, t1, w));
        }
        float mn0 = fmaxf(m0, t0), mn1 = fmaxf(m1, t1);
        float al0 = __expf(m0 - mn0), al1 = __expf(m1 - mn1);
        m0 = mn0; m1 = mn1;

        float rs0 = 0.0f, rs1 = 0.0f;
        __syncwarp();
#pragma unroll
        for (int nt = 0; nt < 8; nt++) {
            float p0 = __expf(sacc[nt][0] - m0);
            float p1 = __expf(sacc[nt][1] - m0);
            float p2 = __expf(sacc[nt][2] - m1);
            float p3 = __expf(sacc[nt][3] - m1);
            rs0 += p0 + p1; rs1 += p2 + p3;
            const int col = nt * 8 + 2 * c;
            *(float2*)&Ps[(qr + g) * FKP + col]     = make_float2(tf32f(p0), tf32f(p1));
            *(float2*)&Ps[(qr + g + 8) * FKP + col] = make_float2(tf32f(p2), tf32f(p3));
        }
#pragma unroll
        for (int w = 1; w <= 2; w <<= 1) {
            rs0 += __shfl_xor_sync(0xffffffffu, rs0, w);
            rs1 += __shfl_xor_sync(0xffffffffu, rs1, w);
        }
        l0 = l0 * al0 + rs0;
        l1 = l1 * al1 + rs1;
#pragma unroll
        for (int nt = 0; nt < 8; nt++) {
            oacc[nt][0] *= al0; oacc[nt][1] *= al0;
            oacc[nt][2] *= al1; oacc[nt][3] *= al1;
        }
        __syncwarp();

        // O += P V
#pragma unroll
        for (int ks = 0; ks < 8; ks++) {
            const int kk = ks * 8;
            unsigned pf0 = __float_as_uint(Ps[(qr + g) * FKP + kk + c]);
            unsigned pf1 = __float_as_uint(Ps[(qr + g + 8) * FKP + kk + c]);
            unsigned pf2 = __float_as_uint(Ps[(qr + g) * FKP + kk + c + 4]);
            unsigned pf3 = __float_as_uint(Ps[(qr + g + 8) * FKP + kk + c + 4]);
#pragma unroll
            for (int nt = 0; nt < 8; nt++) {
                unsigned b0 = __float_as_uint(Vs[(kk + c) * FVP + nt * 8 + g]);
                unsigned b1 = __float_as_uint(Vs[(kk + c + 4) * FVP + nt * 8 + g]);
                mma_tf32(oacc[nt], pf0, pf1, pf2, pf3, b0, b1);
            }
        }
    }

    // Epilogue: normalize, scatter heads back into [B,T,C]
    const int b = bh / HH;
    const int h = bh % HH;
    const float inv0 = 1.0f / l0, inv1 = 1.0f / l1;
    const int row0 = qbase + qr + g;
#pragma unroll
    for (int nt = 0; nt < 8; nt++) {
        const int col = h * 64 + nt * 8 + 2 * c;
        *(float2*)(g_y + (size_t)(b * TT + row0) * CC + col) =
            make_float2(oacc[nt][0] * inv0, oacc[nt][1] * inv0);
        *(float2*)(g_y + (size_t)(b * TT + row0 + 8) * CC + col) =
            make_float2(oacc[nt][2] * inv1, oacc[nt][3] * inv1);
    }
}

// ---------------------------------------------------------------------------
extern "C" void kernel_launch(void* const* d_in, const int* in_sizes, int n_in,
                              void* d_out, int out_size)
{
    const float* x      = (const float*)d_in[0];
    const float* w_attn = (const float*)d_in[1];
    const float* w_proj = (const float*)d_in[2];
    float* out = (float*)d_out;

    float *qkv, *y;
    cudaGetSymbolAddress((void**)&qkv, g_qkv);
    cudaGetSymbolAddress((void**)&y, g_y);

    // 1) QKV projection: [4096,3072]; 24x16 = 384 blocks
    mma_gemm_v3<<<dim3(3 * CC / 128, BB * TT / 256), 512>>>(x, w_attn, qkv,
                                                            BB * TT, 3 * CC, CC);
    // 2) RMSNorm + RoPE + head split (tf32-rounded outputs)
    norm_rope_kernel<<<dim3(BB * TT, HH / 4), dim3(32, 4)>>>(qkv);

    // 3) Causal flash attention
    cudaFuncSetAttribute(flash_mma2, cudaFuncAttributeMaxDynamicSharedMemorySize,
                         FLASH2_SMEM_BYTES);
    flash_mma2<<<dim3(TT / 128, BB * HH), 256, FLASH2_SMEM_BYTES>>>();

    // 4) Output projection: [4096,1024]; 8x16 = 128 blocks (single wave)
    mma_gemm_v3<<<dim3(CC / 128, BB * TT / 256), 512>>>(y, w_proj, out,
                                                        BB * TT, CC, CC);
}

// round 9
// speedup vs baseline: 1.1914x; 1.1914x over previous
#include <cuda_runtime.h>
#include <math.h>
#include <stdint.h>

// Problem constants
#define BB 2
#define TT 2048
#define HH 16
#define DD 64
#define CC 1024

// Scratch (device globals: allocation-free per harness rules)
__device__ float g_qkv[BB * TT * 3 * CC];
__device__ float g_q[BB * HH * TT * DD];
__device__ float g_k[BB * HH * TT * DD];
__device__ float g_v[BB * HH * TT * DD];
__device__ float g_y[BB * TT * CC];
__device__ float g_xr[BB * TT * CC];       // tf32-rounded x
__device__ float g_war[3 * CC * CC];       // tf32-rounded w_attn
__device__ float g_wpr[CC * CC];           // tf32-rounded w_proj

// ---------------------------------------------------------------------------
// tf32 / mma / async helpers
// ---------------------------------------------------------------------------
__device__ __forceinline__ unsigned tf32u(float x) {
    unsigned u;
    asm("cvt.rna.tf32.f32 %0, %1;" : "=r"(u) : "f"(x));
    return u;
}
__device__ __forceinline__ float tf32f(float x) {
    return __uint_as_float(tf32u(x));
}

__device__ __forceinline__ void mma_tf32(float* d,
    unsigned a0, unsigned a1, unsigned a2, unsigned a3,
    unsigned b0, unsigned b1)
{
    asm volatile(
        "mma.sync.aligned.m16n8k8.row.col.f32.tf32.tf32.f32 "
        "{%0,%1,%2,%3}, {%4,%5,%6,%7}, {%8,%9}, {%0,%1,%2,%3};\n"
        : "+f"(d[0]), "+f"(d[1]), "+f"(d[2]), "+f"(d[3])
        : "r"(a0), "r"(a1), "r"(a2), "r"(a3), "r"(b0), "r"(b1));
}

// ldmatrix x4 (b16 view; one m8n8x4 = 4 tf32 8x4 chunks)
__device__ __forceinline__ void ldsm_x4(unsigned& r0, unsigned& r1,
                                        unsigned& r2, unsigned& r3, uint32_t a)
{
    asm volatile("ldmatrix.sync.aligned.m8n8.x4.shared.b16 {%0,%1,%2,%3}, [%4];"
                 : "=r"(r0), "=r"(r1), "=r"(r2), "=r"(r3) : "r"(a));
}

__device__ __forceinline__ void cp16(uint32_t s, const void* g) {
    asm volatile("cp.async.cg.shared.global [%0], [%1], 16;\n" :: "r"(s), "l"(g));
}
__device__ __forceinline__ void cp_commit() {
    asm volatile("cp.async.commit_group;\n");
}
__device__ __forceinline__ void cp_wait0() {
    asm volatile("cp.async.wait_group 0;\n" ::: "memory");
}

// ---------------------------------------------------------------------------
// RNA-round a float array to tf32 (elementwise), float4 granularity.
// ---------------------------------------------------------------------------
__global__ void round_tf32_kernel(const float4* __restrict__ src,
                                  float4* __restrict__ dst, int n4)
{
    int i = blockIdx.x * blockDim.x + threadIdx.x;
    if (i < n4) {
        float4 v = src[i];
        dst[i] = make_float4(tf32f(v.x), tf32f(v.y), tf32f(v.z), tf32f(v.w));
    }
}

// ---------------------------------------------------------------------------
// tf32 tensor-core GEMM: C[m][n] = sum_k A[m][k]*B[n][k]   (C = A*B^T)
// 128x128 block tile, BK=32, 256 threads (8 warps), warp tile 64x32.
// cp.async double-buffered; inputs MUST be pre-rounded tf32 (raw bits in smem,
// fragments fetched via ldmatrix -> pure LDSM + HMMA inner loop).
// ---------------------------------------------------------------------------
#define GP 36   // pitch: row starts at banks 4r%32 -> conflict-free LDSM

__global__ __launch_bounds__(256) void mma_gemm_abt(
    const float* __restrict__ A, const float* __restrict__ Bm,
    float* __restrict__ Cm, int M, int N, int K)
{
    __shared__ __align__(16) float As[2][128 * GP];
    __shared__ __align__(16) float Bs[2][128 * GP];

    const int tid  = threadIdx.x;
    const int warp = tid >> 5;
    const int lane = tid & 31;
    const int g = lane >> 2;
    const int c = lane & 3;

    const int wm = (warp & 1) * 64;
    const int wn = (warp >> 1) * 32;

    const int bm = blockIdx.y * 128;
    const int bn = blockIdx.x * 128;

    const int lrow = tid >> 3;         // 0..31
    const int lcol = (tid & 7) * 4;    // 0..28

    const uint32_t as_s = (uint32_t)__cvta_generic_to_shared(As);
    const uint32_t bs_s = (uint32_t)__cvta_generic_to_shared(Bs);
    const uint32_t bufB = 128 * GP * 4;

    // ldmatrix lane-address components
    const int aRowL = lane & 15;             // row within 16-row A group
    const int aColL = (lane >> 4) * 4;       // k-chunk select (0 or 4)
    const int bRowL = (lane & 7) + ((lane >> 4) << 3);   // row within 16-row B group
    const int bColL = ((lane >> 3) & 1) * 4;             // k-chunk select
    const uint32_t aAddr0 = as_s + (uint32_t)((wm + aRowL) * GP + aColL) * 4;
    const uint32_t bAddr0 = bs_s + (uint32_t)((wn + bRowL) * GP + bColL) * 4;

    // Prefetch k-tile 0 into buffer 0
#pragma unroll
    for (int i = 0; i < 4; i++) {
        const uint32_t so = (uint32_t)((lrow + i * 32) * GP + lcol) * 4;
        cp16(as_s + so, A + (size_t)(bm + lrow + i * 32) * K + lcol);
        cp16(bs_s + so, Bm + (size_t)(bn + lrow + i * 32) * K + lcol);
    }
    cp_commit();

    float acc[4][4][4];
#pragma unroll
    for (int i = 0; i < 4; i++)
#pragma unroll
        for (int j = 0; j < 4; j++)
#pragma unroll
            for (int r = 0; r < 4; r++) acc[i][j][r] = 0.0f;

    int buf = 0;
    for (int k0 = 0; k0 < K; k0 += 32, buf ^= 1) {
        cp_wait0();
        __syncthreads();

        if (k0 + 32 < K) {
            const uint32_t bo = (buf ^ 1) * bufB;
#pragma unroll
            for (int i = 0; i < 4; i++) {
                const uint32_t so = bo + (uint32_t)((lrow + i * 32) * GP + lcol) * 4;
                cp16(as_s + so, A + (size_t)(bm + lrow + i * 32) * K + k0 + 32 + lcol);
                cp16(bs_s + so, Bm + (size_t)(bn + lrow + i * 32) * K + k0 + 32 + lcol);
            }
            cp_commit();
        }

        const uint32_t aB = aAddr0 + buf * bufB;
        const uint32_t bB = bAddr0 + buf * bufB;
#pragma unroll
        for (int ks = 0; ks < 4; ks++) {
            const int kk = ks * 8;
            unsigned af[4][4];
#pragma unroll
            for (int mt = 0; mt < 4; mt++)
                ldsm_x4(af[mt][0], af[mt][1], af[mt][2], af[mt][3],
                        aB + (uint32_t)(mt * 16 * GP + kk) * 4);
            unsigned bf[4][2];
#pragma unroll
            for (int ntp = 0; ntp < 2; ntp++)
                ldsm_x4(bf[2 * ntp][0], bf[2 * ntp][1],
                        bf[2 * ntp + 1][0], bf[2 * ntp + 1][1],
                        bB + (uint32_t)(ntp * 16 * GP + kk) * 4);
#pragma unroll
            for (int mt = 0; mt < 4; mt++)
#pragma unroll
                for (int nt = 0; nt < 4; nt++)
                    mma_tf32(acc[mt][nt], af[mt][0], af[mt][1], af[mt][2], af[mt][3],
                             bf[nt][0], bf[nt][1]);
        }
    }

#pragma unroll
    for (int mt = 0; mt < 4; mt++) {
        const int r0 = bm + wm + mt * 16 + g;
#pragma unroll
        for (int nt = 0; nt < 4; nt++) {
            const int c0 = bn + wn + nt * 8 + 2 * c;
            *(float2*)(Cm + (size_t)r0 * N + c0) = make_float2(acc[mt][nt][0], acc[mt][nt][1]);
            *(float2*)(Cm + (size_t)(r0 + 8) * N + c0) = make_float2(acc[mt][nt][2], acc[mt][nt][3]);
        }
    }
}

// ---------------------------------------------------------------------------
// RMSNorm(q,k) + RoPE + head-split into [B,H,T,D]; outputs tf32-rounded.
// ---------------------------------------------------------------------------
__global__ void norm_rope_kernel(const float* __restrict__ qkv)
{
    const int lane = threadIdx.x;
    const int h = blockIdx.y * 4 + threadIdx.y;
    const int bt = blockIdx.x;
    const int b = bt / TT;
    const int t = bt % TT;

    const float* row = qkv + (size_t)bt * 3 * CC;
    float q0 = row[h * 64 + lane],           q1 = row[h * 64 + lane + 32];
    float k0 = row[CC + h * 64 + lane],      k1 = row[CC + h * 64 + lane + 32];
    float v0 = row[2 * CC + h * 64 + lane],  v1 = row[2 * CC + h * 64 + lane + 32];

    float qs = q0 * q0 + q1 * q1;
    float ks = k0 * k0 + k1 * k1;
#pragma unroll
    for (int w = 16; w >= 1; w >>= 1) {
        qs += __shfl_xor_sync(0xffffffffu, qs, w);
        ks += __shfl_xor_sync(0xffffffffu, ks, w);
    }
    const float eps = 1.1920929e-7f;
    float qr = rsqrtf(qs * (1.0f / 64.0f) + eps);
    float kr = rsqrtf(ks * (1.0f / 64.0f) + eps);
    q0 *= qr; q1 *= qr; k0 *= kr; k1 *= kr;

    float inv = powf(10000.0f, -(float)lane * (1.0f / 32.0f));
    float ang = (float)t * inv;
    float sn, cs;
    sincosf(ang, &sn, &cs);

    float qo0 = q0 * cs - q1 * sn;
    float qo1 = q1 * cs + q0 * sn;
    float ko0 = k0 * cs - k1 * sn;
    float ko1 = k1 * cs + k0 * sn;

    size_t o = (((size_t)b * HH + h) * TT + t) * DD;
    g_q[o + lane] = tf32f(qo0); g_q[o + lane + 32] = tf32f(qo1);
    g_k[o + lane] = tf32f(ko0); g_k[o + lane + 32] = tf32f(ko1);
    g_v[o + lane] = tf32f(v0);  g_v[o + lane + 32] = tf32f(v1);
}

// ---------------------------------------------------------------------------
// Causal flash attention, tf32 mma + ldmatrix fragments.
// 256 threads (8 warps), 128 q-rows/block, 64-key tiles, cp.async double-buffer.
// K raw [key][d] pitch 68 (ldmatrix B-frags conflict-free).
// V raw [key][d] pitch 72 (scalar B-frags conflict-free).
// Ps [128][68]: Q staging, then per-warp P scratch (ldmatrix A-frags).
// ---------------------------------------------------------------------------
#define FKP 68
#define FVP 72
#define FLASH2_SMEM_BYTES ((128 * FKP + 2 * 64 * FKP + 2 * 64 * FVP) * 4)

__global__ __launch_bounds__(256) void flash_mma2()
{
    extern __shared__ __align__(16) float smem[];
    float* Ps  = smem;                       // [128][FKP]
    float* KsB = smem + 128 * FKP;           // [2][64][FKP]
    float* VsB = KsB + 2 * 64 * FKP;         // [2][64][FVP]

    const int tid  = threadIdx.x;
    const int warp = tid >> 5;
    const int lane = tid & 31;
    const int g = lane >> 2;
    const int c = lane & 3;
    const int qr = warp * 16;

    const int qt = gridDim.x - 1 - blockIdx.x;   // heavy tiles first
    const int bh = blockIdx.y;
    const int qbase = qt * 128;

    const float* Q = g_q + (size_t)bh * TT * DD;
    const float* K = g_k + (size_t)bh * TT * DD;
    const float* V = g_v + (size_t)bh * TT * DD;

    // Stage Q tile [128][64] into Ps
#pragma unroll
    for (int i = 0; i < 8; i++) {
        int idx = tid + i * 256;
        int r = idx >> 4, dv = (idx & 15) * 4;
        *(float4*)&Ps[r * FKP + dv] = *(const float4*)(Q + (size_t)(qbase + r) * 64 + dv);
    }

    const uint32_t ps_s = (uint32_t)__cvta_generic_to_shared(Ps);
    const uint32_t ks_s = (uint32_t)__cvta_generic_to_shared(KsB);
    const uint32_t vs_s = (uint32_t)__cvta_generic_to_shared(VsB);

    // ldmatrix lane-address components
    const int aRowL = lane & 15;
    const int aColL = (lane >> 4) * 4;
    const int bRowL = (lane & 7) + ((lane >> 4) << 3);
    const int bColL = ((lane >> 3) & 1) * 4;
    const uint32_t qAddr = ps_s + (uint32_t)((qr + aRowL) * FKP + aColL) * 4;  // Q & P A-frags
    const uint32_t kAddr0 = ks_s + (uint32_t)(bRowL * FKP + bColL) * 4;        // K B-frags

    // Prefetch K/V tile 0 into buffer 0
#pragma unroll
    for (int i = 0; i < 4; i++) {
        int idx = tid + i * 256;
        int r = idx >> 4, c4 = (idx & 15) * 4;
        cp16(ks_s + (uint32_t)(r * FKP + c4) * 4, K + (size_t)r * 64 + c4);
        cp16(vs_s + (uint32_t)(r * FVP + c4) * 4, V + (size_t)r * 64 + c4);
    }
    cp_commit();
    __syncthreads();

    // Q A-fragments via ldmatrix
    unsigned qf[8][4];
#pragma unroll
    for (int ks = 0; ks < 8; ks++)
        ldsm_x4(qf[ks][0], qf[ks][1], qf[ks][2], qf[ks][3], qAddr + (uint32_t)(ks * 8) * 4);

    float oacc[8][4];
#pragma unroll
    for (int nt = 0; nt < 8; nt++)
#pragma unroll
        for (int r = 0; r < 4; r++) oacc[nt][r] = 0.0f;
    float m0 = -1e30f, m1 = -1e30f, l0 = 0.0f, l1 = 0.0f;

    const int nkt = 2 * qt + 2;
    const int ktmax_w = 2 * qt + (warp >= 4 ? 1 : 0);
    const int q0i = qbase + qr + g;
    const int q1i = q0i + 8;

    for (int kt = 0; kt < nkt; kt++) {
        cp_wait0();
        __syncthreads();

        if (kt + 1 < nkt) {
            const int kb = (kt + 1) * 64;
            const uint32_t bo = (uint32_t)(((kt + 1) & 1) * 64);
#pragma unroll
            for (int i = 0; i < 4; i++) {
                int idx = tid + i * 256;
                int r = idx >> 4, c4 = (idx & 15) * 4;
                cp16(ks_s + ((bo + r) * FKP + c4) * 4, K + (size_t)(kb + r) * 64 + c4);
                cp16(vs_s + ((bo + r) * FVP + c4) * 4, V + (size_t)(kb + r) * 64 + c4);
            }
            cp_commit();
        }

        if (kt > ktmax_w) continue;

        const uint32_t kB = kAddr0 + (uint32_t)((kt & 1) * 64 * FKP) * 4;
        const float* Vs = VsB + (kt & 1) * 64 * FVP;

        // S = Q K^T  (B-frags via ldmatrix: 2 nt per LDSM)
        float sacc[8][4];
#pragma unroll
        for (int nt = 0; nt < 8; nt++)
#pragma unroll
            for (int r = 0; r < 4; r++) sacc[nt][r] = 0.0f;

#pragma unroll
        for (int ks = 0; ks < 8; ks++) {
            const int kk = ks * 8;
#pragma unroll
            for (int ntp = 0; ntp < 4; ntp++) {
                unsigned b0a, b1a, b0b, b1b;
                ldsm_x4(b0a, b1a, b0b, b1b, kB + (uint32_t)(ntp * 16 * FKP + kk) * 4);
                mma_tf32(sacc[2 * ntp],     qf[ks][0], qf[ks][1], qf[ks][2], qf[ks][3], b0a, b1a);
                mma_tf32(sacc[2 * ntp + 1], qf[ks][0], qf[ks][1], qf[ks][2], qf[ks][3], b0b, b1b);
            }
        }

        // scale + causal mask
        const bool diag = (kt >= 2 * qt);
#pragma unroll
        for (int nt = 0; nt < 8; nt++) {
#pragma unroll
            for (int r = 0; r < 4; r++) sacc[nt][r] *= 0.125f;
            if (diag) {
                const int key0 = kt * 64 + nt * 8 + 2 * c;
                if (key0 > q0i)     sacc[nt][0] = -1e30f;
                if (key0 + 1 > q0i) sacc[nt][1] = -1e30f;
                if (key0 > q1i)     sacc[nt][2] = -1e30f;
                if (key0 + 1 > q1i) sacc[nt][3] = -1e30f;
            }
        }

        // online softmax
        float t0 = -1e30f, t1 = -1e30f;
#pragma unroll
        for (int nt = 0; nt < 8; nt++) {
            t0 = fmaxf(t0, fmaxf(sacc[nt][0], sacc[nt][1]));
            t1 = fmaxf(t1, fmaxf(sacc[nt][2], sacc[nt][3]));
        }
#pragma unroll
        for (int w = 1; w <= 2; w <<= 1) {
            t0 = fmaxf(t0, __shfl_xor_sync(0xffffffffu, t0, w));
            t1 = fmaxf(t1, __shfl_xor_sync(0xffffffffu, t1, w));
        }
        float mn0 = fmaxf(m0, t0), mn1 = fmaxf(m1, t1);
        float al0 = __expf(m0 - mn0), al1 = __expf(m1 - mn1);
        m0 = mn0; m1 = mn1;

        float rs0 = 0.0f, rs1 = 0.0f;
        __syncwarp();
#pragma unroll
        for (int nt = 0; nt < 8; nt++) {
            float p0 = __expf(sacc[nt][0] - m0);
            float p1 = __expf(sacc[nt][1] - m0);
            float p2 = __expf(sacc[nt][2] - m1);
            float p3 = __expf(sacc[nt][3] - m1);
            rs0 += p0 + p1; rs1 += p2 + p3;
            const int col = nt * 8 + 2 * c;
            *(float2*)&Ps[(qr + g) * FKP + col]     = make_float2(tf32f(p0), tf32f(p1));
            *(float2*)&Ps[(qr + g + 8) * FKP + col] = make_float2(tf32f(p2), tf32f(p3));
        }
#pragma unroll
        for (int w = 1; w <= 2; w <<= 1) {
            rs0 += __shfl_xor_sync(0xffffffffu, rs0, w);
            rs1 += __shfl_xor_sync(0xffffffffu, rs1, w);
        }
        l0 = l0 * al0 + rs0;
        l1 = l1 * al1 + rs1;
#pragma unroll
        for (int nt = 0; nt < 8; nt++) {
            oacc[nt][0] *= al0; oacc[nt][1] *= al0;
            oacc[nt][2] *= al1; oacc[nt][3] *= al1;
        }
        __syncwarp();   // P visible to whole warp

        // O += P V  (P A-frags via ldmatrix)
#pragma unroll
        for (int ks = 0; ks < 8; ks++) {
            const int kk = ks * 8;
            unsigned pf0, pf1, pf2, pf3;
            ldsm_x4(pf0, pf1, pf2, pf3, qAddr + (uint32_t)kk * 4);
#pragma unroll
            for (int nt = 0; nt < 8; nt++) {
                unsigned b0 = __float_as_uint(Vs[(kk + c) * FVP + nt * 8 + g]);
                unsigned b1 = __float_as_uint(Vs[(kk + c + 4) * FVP + nt * 8 + g]);
                mma_tf32(oacc[nt], pf0, pf1, pf2, pf3, b0, b1);
            }
        }
    }

    // Epilogue: normalize, tf32-round (GEMM2 consumes y via LDSM raw),
    // scatter heads back into [B,T,C]
    const int b = bh / HH;
    const int h = bh % HH;
    const float inv0 = 1.0f / l0, inv1 = 1.0f / l1;
    const int row0 = qbase + qr + g;
#pragma unroll
    for (int nt = 0; nt < 8; nt++) {
        const int col = h * 64 + nt * 8 + 2 * c;
        *(float2*)(g_y + (size_t)(b * TT + row0) * CC + col) =
            make_float2(tf32f(oacc[nt][0] * inv0), tf32f(oacc[nt][1] * inv0));
        *(float2*)(g_y + (size_t)(b * TT + row0 + 8) * CC + col) =
            make_float2(tf32f(oacc[nt][2] * inv1), tf32f(oacc[nt][3] * inv1));
    }
}

// ---------------------------------------------------------------------------
extern "C" void kernel_launch(void* const* d_in, const int* in_sizes, int n_in,
                              void* d_out, int out_size)
{
    const float* x      = (const float*)d_in[0];
    const float* w_attn = (const float*)d_in[1];
    const float* w_proj = (const float*)d_in[2];
    float* out = (float*)d_out;

    float *qkv, *y, *xr, *war, *wpr;
    cudaGetSymbolAddress((void**)&qkv, g_qkv);
    cudaGetSymbolAddress((void**)&y,   g_y);
    cudaGetSymbolAddress((void**)&xr,  g_xr);
    cudaGetSymbolAddress((void**)&war, g_war);
    cudaGetSymbolAddress((void**)&wpr, g_wpr);

    // 0) RNA-round GEMM inputs to tf32 (numerics identical to cvt-on-load)
    round_tf32_kernel<<<(BB * TT * CC / 4 + 255) / 256, 256>>>(
        (const float4*)x, (float4*)xr, BB * TT * CC / 4);
    round_tf32_kernel<<<(3 * CC * CC / 4 + 255) / 256, 256>>>(
        (const float4*)w_attn, (float4*)war, 3 * CC * CC / 4);
    round_tf32_kernel<<<(CC * CC / 4 + 255) / 256, 256>>>(
        (const float4*)w_proj, (float4*)wpr, CC * CC / 4);

    // 1) QKV projection: [4096,3072]
    mma_gemm_abt<<<dim3(3 * CC / 128, BB * TT / 128), 256>>>(xr, war, qkv,
                                                             BB * TT, 3 * CC, CC);
    // 2) RMSNorm + RoPE + head split (tf32-rounded outputs)
    norm_rope_kernel<<<dim3(BB * TT, HH / 4), dim3(32, 4)>>>(qkv);

    // 3) Causal flash attention
    cudaFuncSetAttribute(flash_mma2, cudaFuncAttributeMaxDynamicSharedMemorySize,
                         FLASH2_SMEM_BYTES);
    flash_mma2<<<dim3(TT / 128, BB * HH), 256, FLASH2_SMEM_BYTES>>>();

    // 4) Output projection: [4096,1024]
    mma_gemm_abt<<<dim3(CC / 128, BB * TT / 128), 256>>>(y, wpr, out,
                                                         BB * TT, CC, CC);
}

// round 14
// speedup vs baseline: 1.9989x; 1.6778x over previous
#include <cuda_runtime.h>
#include <cuda_fp16.h>
#include <math.h>
#include <stdint.h>

// Problem constants
#define BB 2
#define TT 2048
#define HH 16
#define DD 64
#define CC 1024

// Scratch (device globals: allocation-free per harness rules)
__device__ float  g_qkv[BB * TT * 3 * CC];
__device__ __half g_q[BB * HH * TT * DD];
__device__ __half g_k[BB * HH * TT * DD];
__device__ __half g_v[BB * HH * TT * DD];
__device__ __half g_y[BB * TT * CC];
__device__ __half g_xr[BB * TT * CC];       // fp16-rounded x
__device__ __half g_war[3 * CC * CC];       // fp16-rounded w_attn
__device__ __half g_wpr[CC * CC];           // fp16-rounded w_proj

// ---------------------------------------------------------------------------
// mma / ldmatrix / async helpers (fp16, fp32 accumulate)
// ---------------------------------------------------------------------------
__device__ __forceinline__ void mma_f16(float* d,
    unsigned a0, unsigned a1, unsigned a2, unsigned a3,
    unsigned b0, unsigned b1)
{
    asm volatile(
        "mma.sync.aligned.m16n8k16.row.col.f32.f16.f16.f32 "
        "{%0,%1,%2,%3}, {%4,%5,%6,%7}, {%8,%9}, {%0,%1,%2,%3};\n"
        : "+f"(d[0]), "+f"(d[1]), "+f"(d[2]), "+f"(d[3])
        : "r"(a0), "r"(a1), "r"(a2), "r"(a3), "r"(b0), "r"(b1));
}

__device__ __forceinline__ void ldsm_x4(unsigned& r0, unsigned& r1,
                                        unsigned& r2, unsigned& r3, uint32_t a)
{
    asm volatile("ldmatrix.sync.aligned.m8n8.x4.shared.b16 {%0,%1,%2,%3}, [%4];"
                 : "=r"(r0), "=r"(r1), "=r"(r2), "=r"(r3) : "r"(a));
}
__device__ __forceinline__ void ldsm_x4_t(unsigned& r0, unsigned& r1,
                                          unsigned& r2, unsigned& r3, uint32_t a)
{
    asm volatile("ldmatrix.sync.aligned.m8n8.x4.trans.shared.b16 {%0,%1,%2,%3}, [%4];"
                 : "=r"(r0), "=r"(r1), "=r"(r2), "=r"(r3) : "r"(a));
}

__device__ __forceinline__ void cp16(uint32_t s, const void* g) {
    asm volatile("cp.async.cg.shared.global [%0], [%1], 16;\n" :: "r"(s), "l"(g));
}
__device__ __forceinline__ void cp_commit() {
    asm volatile("cp.async.commit_group;\n");
}
__device__ __forceinline__ void cp_wait0() {
    asm volatile("cp.async.wait_group 0;\n" ::: "memory");
}

// ---------------------------------------------------------------------------
// RN-round float array to fp16.
// ---------------------------------------------------------------------------
__global__ void round_f16_kernel(const float4* __restrict__ src,
                                 __half2* __restrict__ dst, int n4)
{
    int i = blockIdx.x * blockDim.x + threadIdx.x;
    if (i < n4) {
        float4 v = src[i];
        dst[2 * i]     = __floats2half2_rn(v.x, v.y);
        dst[2 * i + 1] = __floats2half2_rn(v.z, v.w);
    }
}

// ---------------------------------------------------------------------------
// fp16 tensor-core GEMM: C[m][n] = sum_k A[m][k]*B[n][k]   (C = A*B^T)
// 128x128 block tile, BK=32, 256 threads (8 warps), warp tile 64x32.
// cp.async double-buffered, ldmatrix fragments, m16n8k16 HMMA, fp32 acc.
// ---------------------------------------------------------------------------
#define GPH 40   // smem pitch in halves (80B): banks 20r%32 distinct per 8 rows

__global__ __launch_bounds__(256) void hgemm_abt(
    const __half* __restrict__ A, const __half* __restrict__ Bm,
    float* __restrict__ Cm, int M, int N, int K)
{
    __shared__ __align__(16) __half As[2][128 * GPH];
    __shared__ __align__(16) __half Bs[2][128 * GPH];

    const int tid  = threadIdx.x;
    const int warp = tid >> 5;
    const int lane = tid & 31;
    const int g = lane >> 2;
    const int c = lane & 3;

    const int wm = (warp & 1) * 64;
    const int wn = (warp >> 1) * 32;

    const int bm = blockIdx.y * 128;
    const int bn = blockIdx.x * 128;

    // Load mapping: tile 128 rows x 32 halves = 512 16B chunks per matrix;
    // 256 threads -> 2 chunks each (rows lrow, lrow+64), full coverage.
    const int lrow = tid >> 2;              // 0..63
    const int lch  = (tid & 3) * 8;         // half-col 0,8,16,24

    const uint32_t as_s = (uint32_t)__cvta_generic_to_shared(As);
    const uint32_t bs_s = (uint32_t)__cvta_generic_to_shared(Bs);
    const uint32_t bufB = 128 * GPH * 2;

    // ldmatrix lane-address components
    const int aRowL = lane & 15;                          // A-style
    const int aColB = (lane >> 4) * 16;                   // byte col
    const int bRowL = (lane & 7) + ((lane >> 4) << 3);    // B-style
    const int bColB = ((lane >> 3) & 1) * 16;
    const uint32_t aAddr0 = as_s + (uint32_t)((wm + aRowL) * GPH) * 2 + aColB;
    const uint32_t bAddr0 = bs_s + (uint32_t)((wn + bRowL) * GPH) * 2 + bColB;

    // Prefetch k-tile 0 into buffer 0
#pragma unroll
    for (int i = 0; i < 2; i++) {
        const int r = lrow + i * 64;
        const uint32_t so = (uint32_t)(r * GPH + lch) * 2;
        cp16(as_s + so, A + (size_t)(bm + r) * K + lch);
        cp16(bs_s + so, Bm + (size_t)(bn + r) * K + lch);
    }
    cp_commit();

    float acc[4][4][4];
#pragma unroll
    for (int i = 0; i < 4; i++)
#pragma unroll
        for (int j = 0; j < 4; j++)
#pragma unroll
            for (int r = 0; r < 4; r++) acc[i][j][r] = 0.0f;

    int buf = 0;
    for (int k0 = 0; k0 < K; k0 += 32, buf ^= 1) {
        cp_wait0();
        __syncthreads();

        if (k0 + 32 < K) {
            const uint32_t bo = (buf ^ 1) * bufB;
#pragma unroll
            for (int i = 0; i < 2; i++) {
                const int r = lrow + i * 64;
                const uint32_t so = bo + (uint32_t)(r * GPH + lch) * 2;
                cp16(as_s + so, A + (size_t)(bm + r) * K + k0 + 32 + lch);
                cp16(bs_s + so, Bm + (size_t)(bn + r) * K + k0 + 32 + lch);
            }
            cp_commit();
        }

        const uint32_t aB = aAddr0 + buf * bufB;
        const uint32_t bB = bAddr0 + buf * bufB;
#pragma unroll
        for (int ks = 0; ks < 2; ks++) {
            const uint32_t ko = (uint32_t)(ks * 32);    // 16 halves = 32B
            unsigned af[4][4];
#pragma unroll
            for (int mt = 0; mt < 4; mt++)
                ldsm_x4(af[mt][0], af[mt][1], af[mt][2], af[mt][3],
                        aB + (uint32_t)(mt * 16 * GPH) * 2 + ko);
            unsigned bf[4][2];
#pragma unroll
            for (int p = 0; p < 2; p++)
                ldsm_x4(bf[2 * p][0], bf[2 * p][1], bf[2 * p + 1][0], bf[2 * p + 1][1],
                        bB + (uint32_t)(p * 16 * GPH) * 2 + ko);
#pragma unroll
            for (int mt = 0; mt < 4; mt++)
#pragma unroll
                for (int nt = 0; nt < 4; nt++)
                    mma_f16(acc[mt][nt], af[mt][0], af[mt][1], af[mt][2], af[mt][3],
                            bf[nt][0], bf[nt][1]);
        }
    }

#pragma unroll
    for (int mt = 0; mt < 4; mt++) {
        const int r0 = bm + wm + mt * 16 + g;
#pragma unroll
        for (int nt = 0; nt < 4; nt++) {
            const int c0 = bn + wn + nt * 8 + 2 * c;
            *(float2*)(Cm + (size_t)r0 * N + c0) = make_float2(acc[mt][nt][0], acc[mt][nt][1]);
            *(float2*)(Cm + (size_t)(r0 + 8) * N + c0) = make_float2(acc[mt][nt][2], acc[mt][nt][3]);
        }
    }
}

// ---------------------------------------------------------------------------
// RMSNorm(q,k) + RoPE + head-split into [B,H,T,D]; fp16 outputs.
// ---------------------------------------------------------------------------
__global__ void norm_rope_kernel(const float* __restrict__ qkv)
{
    const int lane = threadIdx.x;
    const int h = blockIdx.y * 4 + threadIdx.y;
    const int bt = blockIdx.x;
    const int b = bt / TT;
    const int t = bt % TT;

    const float* row = qkv + (size_t)bt * 3 * CC;
    float q0 = row[h * 64 + lane],           q1 = row[h * 64 + lane + 32];
    float k0 = row[CC + h * 64 + lane],      k1 = row[CC + h * 64 + lane + 32];
    float v0 = row[2 * CC + h * 64 + lane],  v1 = row[2 * CC + h * 64 + lane + 32];

    float qs = q0 * q0 + q1 * q1;
    float ks = k0 * k0 + k1 * k1;
#pragma unroll
    for (int w = 16; w >= 1; w >>= 1) {
        qs += __shfl_xor_sync(0xffffffffu, qs, w);
        ks += __shfl_xor_sync(0xffffffffu, ks, w);
    }
    const float eps = 1.1920929e-7f;
    float qr = rsqrtf(qs * (1.0f / 64.0f) + eps);
    float kr = rsqrtf(ks * (1.0f / 64.0f) + eps);
    q0 *= qr; q1 *= qr; k0 *= kr; k1 *= kr;

    float inv = powf(10000.0f, -(float)lane * (1.0f / 32.0f));
    float ang = (float)t * inv;
    float sn, cs;
    sincosf(ang, &sn, &cs);

    float qo0 = q0 * cs - q1 * sn;
    float qo1 = q1 * cs + q0 * sn;
    float ko0 = k0 * cs - k1 * sn;
    float ko1 = k1 * cs + k0 * sn;

    size_t o = (((size_t)b * HH + h) * TT + t) * DD;
    g_q[o + lane] = __float2half_rn(qo0); g_q[o + lane + 32] = __float2half_rn(qo1);
    g_k[o + lane] = __float2half_rn(ko0); g_k[o + lane + 32] = __float2half_rn(ko1);
    g_v[o + lane] = __float2half_rn(v0);  g_v[o + lane + 32] = __float2half_rn(v1);
}

// ---------------------------------------------------------------------------
// Causal flash attention, fp16 mma (m16n8k16), fp32 softmax/acc.
// 256 threads (8 warps), 128 q-rows/block, 64-key tiles, cp.async double-buffer.
// Qs/Ps [128][72]h  (Q staging, then P) — A-frags via ldmatrix.
// Ks    [2][64][72]h (K [key][d])       — S B-frags via ldmatrix.
// Vs    [2][64][72]h (V [key][d])       — PV B-frags via ldmatrix.trans.
// Pitch 72 halves = 144B: banks 4r%32 distinct per 8 rows -> conflict-free.
// ---------------------------------------------------------------------------
#define FPH 72
#define FLASH_SMEM_BYTES ((128 * FPH + 4 * 64 * FPH) * 2)

__global__ __launch_bounds__(256) void flash_h()
{
    extern __shared__ __align__(16) __half smh[];
    __half* Ps  = smh;                     // [128][FPH]
    __half* KsB = smh + 128 * FPH;         // [2][64][FPH]
    __half* VsB = KsB + 2 * 64 * FPH;      // [2][64][FPH]

    const int tid  = threadIdx.x;
    const int warp = tid >> 5;
    const int lane = tid & 31;
    const int g = lane >> 2;
    const int c = lane & 3;
    const int qr = warp * 16;

    const int qt = gridDim.x - 1 - blockIdx.x;   // heavy tiles first
    const int bh = blockIdx.y;
    const int qbase = qt * 128;

    const __half* Q = g_q + (size_t)bh * TT * DD;
    const __half* K = g_k + (size_t)bh * TT * DD;
    const __half* V = g_v + (size_t)bh * TT * DD;

    // Stage Q tile [128][64]h into Ps (16B chunks: 128 rows x 8 -> 4/thread)
#pragma unroll
    for (int i = 0; i < 4; i++) {
        int idx = tid + i * 256;
        int r = idx >> 3, ch = (idx & 7) * 8;
        *(uint4*)&Ps[r * FPH + ch] = *(const uint4*)(Q + (size_t)(qbase + r) * 64 + ch);
    }

    const uint32_t ps_s = (uint32_t)__cvta_generic_to_shared(Ps);
    const uint32_t ks_s = (uint32_t)__cvta_generic_to_shared(KsB);
    const uint32_t vs_s = (uint32_t)__cvta_generic_to_shared(VsB);

    // ldmatrix lane-address components
    const int aRowL = lane & 15;
    const int aColB = (lane >> 4) * 16;
    const int bRowL = (lane & 7) + ((lane >> 4) << 3);
    const int bColB = ((lane >> 3) & 1) * 16;
    const uint32_t qAddr  = ps_s + (uint32_t)((qr + aRowL) * FPH) * 2 + aColB;  // Q/P A-frags
    const uint32_t kAddr0 = ks_s + (uint32_t)(bRowL * FPH) * 2 + bColB;         // K B-frags
    const uint32_t vAddr0 = vs_s + (uint32_t)(aRowL * FPH) * 2 + aColB;         // V B-frags (trans)

    // Prefetch K/V tile 0 into buffer 0 (64 rows x 8 chunks = 512 -> 2/thread)
#pragma unroll
    for (int i = 0; i < 2; i++) {
        int idx = tid + i * 256;
        int r = idx >> 3, ch = (idx & 7) * 8;
        cp16(ks_s + (uint32_t)(r * FPH + ch) * 2, K + (size_t)r * 64 + ch);
        cp16(vs_s + (uint32_t)(r * FPH + ch) * 2, V + (size_t)r * 64 + ch);
    }
    cp_commit();
    __syncthreads();

    // Q A-fragments (4 k16-steps over d=64)
    unsigned qf[4][4];
#pragma unroll
    for (int ks = 0; ks < 4; ks++)
        ldsm_x4(qf[ks][0], qf[ks][1], qf[ks][2], qf[ks][3], qAddr + (uint32_t)(ks * 32));

    float oacc[8][4];
#pragma unroll
    for (int nt = 0; nt < 8; nt++)
#pragma unroll
        for (int r = 0; r < 4; r++) oacc[nt][r] = 0.0f;
    float m0 = -1e30f, m1 = -1e30f, l0 = 0.0f, l1 = 0.0f;

    const int nkt = 2 * qt + 2;
    const int ktmax_w = 2 * qt + (warp >= 4 ? 1 : 0);
    const int q0i = qbase + qr + g;
    const int q1i = q0i + 8;
    const uint32_t bufB = (uint32_t)(64 * FPH) * 2;

    for (int kt = 0; kt < nkt; kt++) {
        cp_wait0();
        __syncthreads();

        if (kt + 1 < nkt) {
            const int kb = (kt + 1) * 64;
            const uint32_t bo = ((kt + 1) & 1) * bufB;
#pragma unroll
            for (int i = 0; i < 2; i++) {
                int idx = tid + i * 256;
                int r = idx >> 3, ch = (idx & 7) * 8;
                cp16(ks_s + bo + (uint32_t)(r * FPH + ch) * 2, K + (size_t)(kb + r) * 64 + ch);
                cp16(vs_s + bo + (uint32_t)(r * FPH + ch) * 2, V + (size_t)(kb + r) * 64 + ch);
            }
            cp_commit();
        }

        if (kt > ktmax_w) continue;

        const uint32_t kB = kAddr0 + (kt & 1) * bufB;
        const uint32_t vB = vAddr0 + (kt & 1) * bufB;

        // S = Q K^T (4 k16-steps, 4 nt-pairs)
        float sacc[8][4];
#pragma unroll
        for (int nt = 0; nt < 8; nt++)
#pragma unroll
            for (int r = 0; r < 4; r++) sacc[nt][r] = 0.0f;

#pragma unroll
        for (int ks = 0; ks < 4; ks++) {
            const uint32_t ko = (uint32_t)(ks * 32);
#pragma unroll
            for (int p = 0; p < 4; p++) {
                unsigned b0a, b1a, b0b, b1b;
                ldsm_x4(b0a, b1a, b0b, b1b, kB + (uint32_t)(p * 16 * FPH) * 2 + ko);
                mma_f16(sacc[2 * p],     qf[ks][0], qf[ks][1], qf[ks][2], qf[ks][3], b0a, b1a);
                mma_f16(sacc[2 * p + 1], qf[ks][0], qf[ks][1], qf[ks][2], qf[ks][3], b0b, b1b);
            }
        }

        // scale + causal mask
        const bool diag = (kt >= 2 * qt);
#pragma unroll
        for (int nt = 0; nt < 8; nt++) {
#pragma unroll
            for (int r = 0; r < 4; r++) sacc[nt][r] *= 0.125f;
            if (diag) {
                const int key0 = kt * 64 + nt * 8 + 2 * c;
                if (key0 > q0i)     sacc[nt][0] = -1e30f;
                if (key0 + 1 > q0i) sacc[nt][1] = -1e30f;
                if (key0 > q1i)     sacc[nt][2] = -1e30f;
                if (key0 + 1 > q1i) sacc[nt][3] = -1e30f;
            }
        }

        // online softmax (quad reduction)
        float t0 = -1e30f, t1 = -1e30f;
#pragma unroll
        for (int nt = 0; nt < 8; nt++) {
            t0 = fmaxf(t0, fmaxf(sacc[nt][0], sacc[nt][1]));
            t1 = fmaxf(t1, fmaxf(sacc[nt][2], sacc[nt][3]));
        }
#pragma unroll
        for (int w = 1; w <= 2; w <<= 1) {
            t0 = fmaxf(t0, __shfl_xor_sync(0xffffffffu, t0, w));
            t1 = fmaxf(t1, __shfl_xor_sync(0xffffffffu, t1, w));
        }
        float mn0 = fmaxf(m0, t0), mn1 = fmaxf(m1, t1);
        float al0 = __expf(m0 - mn0), al1 = __expf(m1 - mn1);
        m0 = mn0; m1 = mn1;

        float rs0 = 0.0f, rs1 = 0.0f;
        __syncwarp();   // prior PV A-frag reads of Ps done (warp-private rows)
#pragma unroll
        for (int nt = 0; nt < 8; nt++) {
            float p0 = __expf(sacc[nt][0] - m0);
            float p1 = __expf(sacc[nt][1] - m0);
            float p2 = __expf(sacc[nt][2] - m1);
            float p3 = __expf(sacc[nt][3] - m1);
            rs0 += p0 + p1; rs1 += p2 + p3;
            const int col = nt * 8 + 2 * c;
            *(__half2*)&Ps[(qr + g) * FPH + col]     = __floats2half2_rn(p0, p1);
            *(__half2*)&Ps[(qr + g + 8) * FPH + col] = __floats2half2_rn(p2, p3);
        }
#pragma unroll
        for (int w = 1; w <= 2; w <<= 1) {
            rs0 += __shfl_xor_sync(0xffffffffu, rs0, w);
            rs1 += __shfl_xor_sync(0xffffffffu, rs1, w);
        }
        l0 = l0 * al0 + rs0;
        l1 = l1 * al1 + rs1;
#pragma unroll
        for (int nt = 0; nt < 8; nt++) {
            oacc[nt][0] *= al0; oacc[nt][1] *= al0;
            oacc[nt][2] *= al1; oacc[nt][3] *= al1;
        }
        __syncwarp();   // P visible to whole warp

        // O += P V (P A-frags ldmatrix; V B-frags ldmatrix.trans: 2 nt per load)
#pragma unroll
        for (int ks = 0; ks < 4; ks++) {
            const uint32_t kro = (uint32_t)(ks * 16 * FPH) * 2;   // 16-key group
            unsigned pf0, pf1, pf2, pf3;
            ldsm_x4(pf0, pf1, pf2, pf3, qAddr + (uint32_t)(ks * 32));
#pragma unroll
            for (int p = 0; p < 4; p++) {
                unsigned b0a, b1a, b0b, b1b;
                ldsm_x4_t(b0a, b1a, b0b, b1b, vB + kro + (uint32_t)(p * 32));
                mma_f16(oacc[2 * p],     pf0, pf1, pf2, pf3, b0a, b1a);
                mma_f16(oacc[2 * p + 1], pf0, pf1, pf2, pf3, b0b, b1b);
            }
        }
    }

    // Epilogue: normalize, fp16-round (GEMM2 consumes y), scatter heads
    const int b = bh / HH;
    const int h = bh % HH;
    const float inv0 = 1.0f / l0, inv1 = 1.0f / l1;
    const int row0 = qbase + qr + g;
#pragma unroll
    for (int nt = 0; nt < 8; nt++) {
        const int col = h * 64 + nt * 8 + 2 * c;
        *(__half2*)(g_y + (size_t)(b * TT + row0) * CC + col) =
            __floats2half2_rn(oacc[nt][0] * inv0, oacc[nt][1] * inv0);
        *(__half2*)(g_y + (size_t)(b * TT + row0 + 8) * CC + col) =
            __floats2half2_rn(oacc[nt][2] * inv1, oacc[nt][3] * inv1);
    }
}

// ---------------------------------------------------------------------------
extern "C" void kernel_launch(void* const* d_in, const int* in_sizes, int n_in,
                              void* d_out, int out_size)
{
    const float* x      = (const float*)d_in[0];
    const float* w_attn = (const float*)d_in[1];
    const float* w_proj = (const float*)d_in[2];
    float* out = (float*)d_out;

    float *qkv;
    __half *y, *xr, *war, *wpr;
    cudaGetSymbolAddress((void**)&qkv, g_qkv);
    cudaGetSymbolAddress((void**)&y,   g_y);
    cudaGetSymbolAddress((void**)&xr,  g_xr);
    cudaGetSymbolAddress((void**)&war, g_war);
    cudaGetSymbolAddress((void**)&wpr, g_wpr);

    // 0) RN-round GEMM inputs to fp16
    round_f16_kernel<<<(BB * TT * CC / 4 + 255) / 256, 256>>>(
        (const float4*)x, (__half2*)xr, BB * TT * CC / 4);
    round_f16_kernel<<<(3 * CC * CC / 4 + 255) / 256, 256>>>(
        (const float4*)w_attn, (__half2*)war, 3 * CC * CC / 4);
    round_f16_kernel<<<(CC * CC / 4 + 255) / 256, 256>>>(
        (const float4*)w_proj, (__half2*)wpr, CC * CC / 4);

    // 1) QKV projection: [4096,3072]
    hgemm_abt<<<dim3(3 * CC / 128, BB * TT / 128), 256>>>(xr, war, qkv,
                                                          BB * TT, 3 * CC, CC);
    // 2) RMSNorm + RoPE + head split (fp16 outputs)
    norm_rope_kernel<<<dim3(BB * TT, HH / 4), dim3(32, 4)>>>(qkv);

    // 3) Causal flash attention (fp16 MMA)
    cudaFuncSetAttribute(flash_h, cudaFuncAttributeMaxDynamicSharedMemorySize,
                         FLASH_SMEM_BYTES);
    flash_h<<<dim3(TT / 128, BB * HH), 256, FLASH_SMEM_BYTES>>>();

    // 4) Output projection: [4096,1024]
    hgemm_abt<<<dim3(CC / 128, BB * TT / 128), 256>>>(y, wpr, out,
                                                      BB * TT, CC, CC);
}